// round 2
// baseline (speedup 1.0000x reference)
#include <cuda_runtime.h>
#include <cstdint>
#include <math.h>

// IMLE sampler: out[s,b,n] = 1 iff (logits[b,n] + Gumbel(noise[s,b,n])) is in
// the row's top-k.  S=16, B=128, N=16384, k=32.
//
// v2: selection on w = (-ln u) * exp(-logit)  (monotone-decreasing in the
// perturbed logit => top-k largest == k smallest w).
//  - E = -ln2*exp(-logit) precomputed once  -> hot loop = 1 MUFU + 1 FMUL/elem
//  - threshold t* = max over warps of per-warp min(w): guarantees >= 32
//    elements with w <= t*  (k=32), no histogram, no per-element atomics
//  - keys live in shared memory (64KB) instead of registers -> 2 CTAs/SM
//  - candidates (w <= t* * e^0.25, ~130/row) exactly recomputed with double
//    log, ranked O(c^2) with lowest-index tie-break (matches jax top_k)
//  - u > 0.9999 guard: fast-log error blows up there; force-collect those
//    and exclude them from the min statistic.

#define NCOLS   16384
#define THREADS 1024
#define CHUNKS  4            // 4 float4 per thread = 16 elements
#define CAP     4096
#define MARGIN_MULT 1.2840254f   // e^0.25 ; fast rel-err on w <= ~2.7e-3
#define UGUARD  0.9999f
#define MAXLROWS 128

__device__ float g_E[MAXLROWS * NCOLS];   // -ln2 * exp(-logit)

__global__ void precompute_E(const float* __restrict__ logits, int n) {
    int i = blockIdx.x * blockDim.x + threadIdx.x;
    if (i < n) g_E[i] = -0.6931471805599453f * __expf(-logits[i]);
}

// float32 log chain, correctly rounded via double (immune to fast-math):
// t1=log(u); t3=log(-t1); p = logit - t3   (matches reference op-by-op)
__device__ __forceinline__ float exact_perturb(float u, float lg) {
    float t1 = (float)log((double)u);
    float t3 = (float)log((double)(-t1));
    return lg + (-t3);
}

extern __shared__ char dynsmem[];

__global__ __launch_bounds__(THREADS, 2)
void imle_topk_kernel(const float* __restrict__ logits,
                      const float* __restrict__ noise,
                      const int* __restrict__ kptr,
                      float* __restrict__ out,
                      int Brows)
{
    float* shw  = (float*)dynsmem;                          // [NCOLS] keys
    int*   cidx = (int*)(dynsmem + NCOLS * 4);              // [CAP]
    float* cval = (float*)(dynsmem + NCOLS * 4 + CAP * 4);  // [CAP]
    __shared__ float wmin_s[32];
    __shared__ float sh_tstar;
    __shared__ int   sh_cnt;

    const int tid  = threadIdx.x;
    const int lane = tid & 31;
    const int warp = tid >> 5;
    const int row  = blockIdx.x;
    const size_t rowoff = (size_t)row * NCOLS;
    const size_t logoff = (size_t)(row % Brows) * NCOLS;

    const float4* n4 = reinterpret_cast<const float4*>(noise + rowoff);
    const float4* e4 = reinterpret_cast<const float4*>(g_E + logoff);
    float4*       o4 = reinterpret_cast<float4*>(out + rowoff);
    float4*       w4 = reinterpret_cast<float4*>(shw);

    // ---- Phase 1: stream noise, compute w keys -> smem, zero output, ----
    // ---- track per-thread min over non-guard elements.                ----
    float mymin = INFINITY;
    const float4 z4 = make_float4(0.f, 0.f, 0.f, 0.f);
    #pragma unroll
    for (int c = 0; c < CHUNKS; ++c) {
        int v = tid + c * THREADS;           // float4 index
        float4 u = __ldcs(&n4[v]);           // streaming (read once)
        float4 E = __ldg(&e4[v]);            // L2-resident across S samples
        float w0 = __log2f(u.x) * E.x;       // (-ln u)*exp(-logit) >= 0
        float w1 = __log2f(u.y) * E.y;
        float w2 = __log2f(u.z) * E.z;
        float w3 = __log2f(u.w) * E.w;
        bool g0 = u.x > UGUARD, g1 = u.y > UGUARD;
        bool g2 = u.z > UGUARD, g3 = u.w > UGUARD;
        float4 s;                            // stored key: guard -> 0 (forced candidate)
        s.x = g0 ? 0.f : w0;  s.y = g1 ? 0.f : w1;
        s.z = g2 ? 0.f : w2;  s.w = g3 ? 0.f : w3;
        w4[v] = s;
        float m0 = g0 ? INFINITY : w0, m1 = g1 ? INFINITY : w1;
        float m2 = g2 ? INFINITY : w2, m3 = g3 ? INFINITY : w3;
        mymin = fminf(mymin, fminf(fminf(m0, m1), fminf(m2, m3)));
        __stcs(&o4[v], z4);
    }

    // ---- Phase 2: t* = max over warps of per-warp min ----
    #pragma unroll
    for (int off = 16; off > 0; off >>= 1)
        mymin = fminf(mymin, __shfl_xor_sync(0xFFFFFFFFu, mymin, off));
    if (lane == 0) wmin_s[warp] = mymin;
    __syncthreads();
    if (warp == 0) {
        float m = wmin_s[lane];
        #pragma unroll
        for (int off = 16; off > 0; off >>= 1)
            m = fmaxf(m, __shfl_xor_sync(0xFFFFFFFFu, m, off));
        if (lane == 0) sh_tstar = m;
    }
    __syncthreads();

    int kk = kptr ? *kptr : 32;
    if (kk < 1) kk = 1;
    if (kk > NCOLS) kk = NCOLS;

    // ---- Phase 3: collect candidates w <= t* * e^M (guards auto-included;
    // ---- widening loop only fires for kk > 32 -- unreachable here).
    float thr = sh_tstar * MARGIN_MULT;
    int cnt;
    for (;;) {
        if (tid == 0) sh_cnt = 0;
        __syncthreads();
        #pragma unroll
        for (int c = 0; c < CHUNKS; ++c) {
            int v = tid + c * THREADS;
            float4 s = w4[v];
            if (s.x <= thr) { int p = atomicAdd(&sh_cnt, 1); if (p < CAP) cidx[p] = 4*v + 0; }
            if (s.y <= thr) { int p = atomicAdd(&sh_cnt, 1); if (p < CAP) cidx[p] = 4*v + 1; }
            if (s.z <= thr) { int p = atomicAdd(&sh_cnt, 1); if (p < CAP) cidx[p] = 4*v + 2; }
            if (s.w <= thr) { int p = atomicAdd(&sh_cnt, 1); if (p < CAP) cidx[p] = 4*v + 3; }
        }
        __syncthreads();
        cnt = sh_cnt < CAP ? sh_cnt : CAP;
        if (sh_cnt >= kk || thr > 1e30f) break;
        thr = fmaxf(thr * 16.0f, 1e-30f);
        __syncthreads();
    }

    // ---- Phase 4: exact recompute for candidates (L2-hot reloads) ----
    for (int i = tid; i < cnt; i += THREADS) {
        int idx = cidx[i];
        float u  = noise[rowoff + idx];
        float lg = logits[logoff + idx];
        cval[i] = exact_perturb(u, lg);
    }
    __syncthreads();

    // ---- Phase 5: exact O(c^2) rank, lowest-index tie-break ----
    for (int i = tid; i < cnt; i += THREADS) {
        float pi = cval[i];
        int   ii = cidx[i];
        int r = 0;
        for (int j = 0; j < cnt; ++j) {
            float pj = cval[j];
            r += (pj > pi) || (pj == pi && cidx[j] < ii);
        }
        if (r < kk) out[rowoff + ii] = 1.0f;
    }
}

extern "C" void kernel_launch(void* const* d_in, const int* in_sizes, int n_in,
                              void* d_out, int out_size) {
    // Identify inputs by size: k is the scalar, noise the largest tensor.
    int iK = -1, iU = -1, iL = -1;
    for (int i = 0; i < n_in; ++i)
        if (in_sizes[i] == 1) iK = i;
    long best = -1;
    for (int i = 0; i < n_in; ++i) {
        if (i == iK) continue;
        if ((long)in_sizes[i] > best) { best = in_sizes[i]; iU = i; }
    }
    for (int i = 0; i < n_in; ++i)
        if (i != iK && i != iU) { iL = i; break; }

    const float* logits = (const float*)d_in[iL];
    const float* noise  = (const float*)d_in[iU];
    const int*   kptr   = (iK >= 0) ? (const int*)d_in[iK] : nullptr;
    float* out = (float*)d_out;

    int rows  = in_sizes[iU] / NCOLS;   // S*B = 2048
    int Brows = in_sizes[iL] / NCOLS;   // B   = 128
    int nlog  = in_sizes[iL];
    if (Brows > MAXLROWS) Brows = MAXLROWS;            // safety for g_E bound
    if (nlog > MAXLROWS * NCOLS) nlog = MAXLROWS * NCOLS;

    precompute_E<<<(nlog + 255) / 256, 256>>>(logits, nlog);

    static bool attr_done = false;
    int dyn = NCOLS * 4 + CAP * 4 + CAP * 4;   // 64KB + 16KB + 16KB = 96KB
    if (!attr_done) {
        cudaFuncSetAttribute(imle_topk_kernel,
                             cudaFuncAttributeMaxDynamicSharedMemorySize, dyn);
        attr_done = true;
    }
    imle_topk_kernel<<<rows, THREADS, dyn>>>(logits, noise, kptr, out, Brows);
}